// round 10
// baseline (speedup 1.0000x reference)
#include <cuda_runtime.h>
#include <cuda_bf16.h>
#include <math.h>

// NNUE HalfKA inference, two-phase, int8-quantized combined table:
//  Phase 1: per feature row f: comb = W_ft[f] + W_fft[f % 768] (fp32),
//           s[f] = maxabs(comb)/127, q[f] = rint(comb/s) as int8  (48 MB table)
//  Phase 2: per batch element, gather 2x32 int8 rows; accumulate
//           acc += float(q) * (v * s[f]) with packed FFMA2; biases fp32; clip;
//           output dot; sigmoid.
//  Rationale: gather phase is LTS-throughput bound (time invariant to occupancy,
//  ~13 TB/s through L2) -> halving bytes/row is the only lever.
//
// Shapes: B=8192, FPP=32, FT_OUT=1024, N_FEAT=49152, N_VFEAT=768.

#define FT_OUT   1024
#define FPP      32
#define NVFEAT   768
#define NFEAT    49152
#define BLD_THREADS 256
#define GTH_THREADS 128   // 128 threads * 8 dims (8 B int8) = one 1024 B row

// 48 MB quantized combined table + per-row scales (static device scratch)
__device__ __align__(16) signed char g_qtab[(size_t)NFEAT * FT_OUT];
__device__ float g_scale[NFEAT];

// ---- packed f32x2 helpers (sm_103a FFMA2 path; ptxas won't emit from C++) ----
__device__ __forceinline__ unsigned long long pack_f2(float a, float b) {
    unsigned long long r;
    asm("mov.b64 %0, {%1, %2};" : "=l"(r) : "f"(a), "f"(b));
    return r;
}
__device__ __forceinline__ void unpack_f2(unsigned long long r, float& a, float& b) {
    asm("mov.b64 {%0, %1}, %2;" : "=f"(a), "=f"(b) : "l"(r));
}
__device__ __forceinline__ unsigned long long fma_f2(unsigned long long a,
                                                     unsigned long long b,
                                                     unsigned long long c) {
    unsigned long long d;
    asm("fma.rn.f32x2 %0, %1, %2, %3;" : "=l"(d) : "l"(a), "l"(b), "l"(c));
    return d;
}
// 8B L1-bypassing load (random gather: L1 hit rate ~0 on 48 MB table)
__device__ __forceinline__ uint2 ldcg8(const void* p) {
    uint2 v;
    asm volatile("ld.global.cg.v2.u32 {%0,%1}, [%2];"
                 : "=r"(v.x), "=r"(v.y) : "l"(p));
    return v;
}

// convert 4 packed int8 -> two f32x2, fma into two accumulators
__device__ __forceinline__ void accum_q4(unsigned int u, unsigned long long vv,
                                         unsigned long long& a0,
                                         unsigned long long& a1) {
    // ptxas folds shifts into I2F byte selectors (I2F.F32.S8 Rs.Bk)
    float f0 = (float)(int)(signed char)(u);
    float f1 = (float)(int)(signed char)(u >> 8);
    float f2 = (float)(int)(signed char)(u >> 16);
    float f3 = (float)(int)(signed char)(u >> 24);
    a0 = fma_f2(pack_f2(f0, f1), vv, a0);
    a1 = fma_f2(pack_f2(f2, f3), vv, a1);
}

// ---------------- Phase 1: build quantized combined table ----------------
__global__ __launch_bounds__(BLD_THREADS)
void build_comb_kernel(const float* __restrict__ W_ft,
                       const float* __restrict__ W_fft)
{
    __shared__ float s_wmax[BLD_THREADS / 32];
    __shared__ float s_inv, s_sc;

    const int f = blockIdx.x;            // 0..NFEAT-1
    const int c = threadIdx.x * 4;       // 0..1020
    const size_t base = (size_t)f * FT_OUT + c;

    // W_ft streamed once: evict-first so it doesn't thrash L2
    const float4 a = __ldcs((const float4*)(W_ft + base));
    const float4 v = __ldg((const float4*)(W_fft + (size_t)(f % NVFEAT) * FT_OUT + c));
    const float w0 = a.x + v.x, w1 = a.y + v.y, w2 = a.z + v.z, w3 = a.w + v.w;

    // block-wide maxabs
    float m = fmaxf(fmaxf(fabsf(w0), fabsf(w1)), fmaxf(fabsf(w2), fabsf(w3)));
    #pragma unroll
    for (int off = 16; off > 0; off >>= 1)
        m = fmaxf(m, __shfl_xor_sync(0xffffffffu, m, off));
    if ((threadIdx.x & 31) == 0) s_wmax[threadIdx.x >> 5] = m;
    __syncthreads();
    if (threadIdx.x == 0) {
        float mm = s_wmax[0];
        #pragma unroll
        for (int k = 1; k < BLD_THREADS / 32; k++) mm = fmaxf(mm, s_wmax[k]);
        mm = fmaxf(mm, 1e-30f);
        s_inv = 127.0f / mm;
        s_sc  = mm / 127.0f;
        g_scale[f] = s_sc;
    }
    __syncthreads();
    const float inv = s_inv;

    char4 q;
    q.x = (signed char)__float2int_rn(w0 * inv);
    q.y = (signed char)__float2int_rn(w1 * inv);
    q.z = (signed char)__float2int_rn(w2 * inv);
    q.w = (signed char)__float2int_rn(w3 * inv);
    *(char4*)(g_qtab + base) = q;
}

// ---------------- Phase 2: gather + epilogue ----------------
__global__ __launch_bounds__(GTH_THREADS, 12)
void nnue_gather_kernel(
    const float* __restrict__ values,     // [NNZ]
    const int*   __restrict__ stm_feat,   // [NNZ]
    const int*   __restrict__ nstm_feat,  // [NNZ]
    const float* __restrict__ b_ft,       // [1024]
    const float* __restrict__ b_fft,      // [1024]
    const float* __restrict__ W_out,      // [2048]
    const float* __restrict__ b_out,      // [1]
    float*       __restrict__ out)        // [B]
{
    __shared__ int s_off[2 * FPP];                     // byte offsets into g_qtab
    __shared__ unsigned long long s_vsp[2 * FPP];      // (v * row_scale) packed f32x2
    __shared__ float s_red[GTH_THREADS / 32];

    const int b   = blockIdx.x;
    const int tid = threadIdx.x;

    if (tid < FPP) {
        const int fs = stm_feat[b * FPP + tid];
        const int fn = nstm_feat[b * FPP + tid];
        const float v = values[b * FPP + tid];
        s_off[tid]       = fs << 10;   // *1024 B/row
        s_off[FPP + tid] = fn << 10;
        const float vs = v * __ldg(g_scale + fs);
        const float vn = v * __ldg(g_scale + fn);
        s_vsp[tid]       = pack_f2(vs, vs);
        s_vsp[FPP + tid] = pack_f2(vn, vn);
    }
    __syncthreads();

    const int d = tid * 8;                 // 8 dims per thread
    const char* base = (const char*)g_qtab + tid * 8;

    // biases -> packed f32x2 accumulators (shared init for both sides)
    unsigned long long acc_s[4], acc_n[4];
    {
        float4 bf0 = *(const float4*)(b_ft  + d);
        float4 bf1 = *(const float4*)(b_ft  + d + 4);
        float4 bb0 = *(const float4*)(b_fft + d);
        float4 bb1 = *(const float4*)(b_fft + d + 4);
        acc_s[0] = pack_f2(bf0.x + bb0.x, bf0.y + bb0.y);
        acc_s[1] = pack_f2(bf0.z + bb0.z, bf0.w + bb0.w);
        acc_s[2] = pack_f2(bf1.x + bb1.x, bf1.y + bb1.y);
        acc_s[3] = pack_f2(bf1.z + bb1.z, bf1.w + bb1.w);
        acc_n[0] = acc_s[0]; acc_n[1] = acc_s[1];
        acc_n[2] = acc_s[2]; acc_n[3] = acc_s[3];
    }

    // Interleaved: 2 independent 8B loads per iter, unroll 4
    #pragma unroll 4
    for (int i = 0; i < FPP; i++) {
        const unsigned long long vvs = s_vsp[i];
        const unsigned long long vvn = s_vsp[FPP + i];
        const uint2 ps = ldcg8(base + s_off[i]);         // 8 int8 stm weights
        const uint2 pn = ldcg8(base + s_off[FPP + i]);   // 8 int8 nstm weights

        accum_q4(ps.x, vvs, acc_s[0], acc_s[1]);
        accum_q4(ps.y, vvs, acc_s[2], acc_s[3]);
        accum_q4(pn.x, vvn, acc_n[0], acc_n[1]);
        accum_q4(pn.y, vvn, acc_n[2], acc_n[3]);
    }

    // unpack, clip, partial output dot — pairwise to keep reg pressure low
    float p = 0.f;
    {
        float a0, a1;
        float4 w;

        w = *(const float4*)(W_out + d);
        unpack_f2(acc_s[0], a0, a1);
        p = fmaf(fminf(fmaxf(a0, 0.f), 1.f), w.x, p);
        p = fmaf(fminf(fmaxf(a1, 0.f), 1.f), w.y, p);
        unpack_f2(acc_s[1], a0, a1);
        p = fmaf(fminf(fmaxf(a0, 0.f), 1.f), w.z, p);
        p = fmaf(fminf(fmaxf(a1, 0.f), 1.f), w.w, p);
        w = *(const float4*)(W_out + d + 4);
        unpack_f2(acc_s[2], a0, a1);
        p = fmaf(fminf(fmaxf(a0, 0.f), 1.f), w.x, p);
        p = fmaf(fminf(fmaxf(a1, 0.f), 1.f), w.y, p);
        unpack_f2(acc_s[3], a0, a1);
        p = fmaf(fminf(fmaxf(a0, 0.f), 1.f), w.z, p);
        p = fmaf(fminf(fmaxf(a1, 0.f), 1.f), w.w, p);

        w = *(const float4*)(W_out + FT_OUT + d);
        unpack_f2(acc_n[0], a0, a1);
        p = fmaf(fminf(fmaxf(a0, 0.f), 1.f), w.x, p);
        p = fmaf(fminf(fmaxf(a1, 0.f), 1.f), w.y, p);
        unpack_f2(acc_n[1], a0, a1);
        p = fmaf(fminf(fmaxf(a0, 0.f), 1.f), w.z, p);
        p = fmaf(fminf(fmaxf(a1, 0.f), 1.f), w.w, p);
        w = *(const float4*)(W_out + FT_OUT + d + 4);
        unpack_f2(acc_n[2], a0, a1);
        p = fmaf(fminf(fmaxf(a0, 0.f), 1.f), w.x, p);
        p = fmaf(fminf(fmaxf(a1, 0.f), 1.f), w.y, p);
        unpack_f2(acc_n[3], a0, a1);
        p = fmaf(fminf(fmaxf(a0, 0.f), 1.f), w.z, p);
        p = fmaf(fminf(fmaxf(a1, 0.f), 1.f), w.w, p);
    }

    // warp reduce (4 warps)
    #pragma unroll
    for (int off = 16; off > 0; off >>= 1)
        p += __shfl_down_sync(0xffffffffu, p, off);
    if ((tid & 31) == 0) s_red[tid >> 5] = p;
    __syncthreads();

    if (tid < (GTH_THREADS / 32)) {
        float q = s_red[tid];
        #pragma unroll
        for (int off = (GTH_THREADS / 64); off > 0; off >>= 1)
            q += __shfl_down_sync(0xfu, q, off);
        if (tid == 0) {
            float x = q + b_out[0];
            out[b] = 1.0f / (1.0f + expf(-x));
        }
    }
}

extern "C" void kernel_launch(void* const* d_in, const int* in_sizes, int n_in,
                              void* d_out, int out_size) {
    // metadata order:
    // 0 values, 1 stm_feat, 2 nstm_feat, 3 batch_idx, 4 W_ft, 5 b_ft,
    // 6 W_fft, 7 b_fft, 8 W_out, 9 b_out, 10 size
    const float* values    = (const float*)d_in[0];
    const int*   stm_feat  = (const int*)d_in[1];
    const int*   nstm_feat = (const int*)d_in[2];
    const float* W_ft      = (const float*)d_in[4];
    const float* b_ft      = (const float*)d_in[5];
    const float* W_fft     = (const float*)d_in[6];
    const float* b_fft     = (const float*)d_in[7];
    const float* W_out     = (const float*)d_in[8];
    const float* b_out     = (const float*)d_in[9];
    float* out = (float*)d_out;

    const int B = out_size;  // 8192

    build_comb_kernel<<<NFEAT, BLD_THREADS>>>(W_ft, W_fft);
    nnue_gather_kernel<<<B, GTH_THREADS>>>(values, stm_feat, nstm_feat,
                                           b_ft, b_fft, W_out, b_out, out);
}

// round 12
// speedup vs baseline: 1.5660x; 1.5660x over previous
#include <cuda_runtime.h>
#include <cuda_bf16.h>
#include <math.h>

// NNUE HalfKA inference, two-phase, int8 table + s16 multipliers + DP2A:
//  Phase 1 (warp-per-row): comb = W_ft[f] + W_fft[f % 768];
//           s[f] = maxabs/127; q[f] = rint(comb/s) int8  (48 MB, L2-resident)
//  Phase 2: per batch element: a_f = v_f * s[feat_f]; T = max|a|;
//           u16_f = rint(a_f * 32767 / T)  (s16, exact to ~3e-5 rel)
//           acc_d  = sum_f q[f,d] * u16_f   -- integer, via PRMT transpose + dp2a
//           hidden = bias + (T/32767) * acc; clip; output dot; sigmoid.
//  Rationale: gather was issue/ALU-bound (~2 slots/weight via I2F); dp2a path
//  is ~1.1 slots/weight with exact integer accumulation.

#define FT_OUT   1024
#define FPP      32
#define NVFEAT   768
#define NFEAT    49152
#define BLD_THREADS 256           // 8 warps = 8 rows per block
#define GTH_THREADS 128           // 128 threads * 8 dims (8 B int8) = one row

// 48 MB quantized combined table + per-row scales (static device scratch)
__device__ __align__(16) signed char g_qtab[(size_t)NFEAT * FT_OUT];
__device__ float g_scale[NFEAT];

__device__ __forceinline__ int dp2a_lo(unsigned a16, unsigned b8, int c) {
    int d;
    asm("dp2a.lo.s32.s32 %0, %1, %2, %3;" : "=r"(d) : "r"(a16), "r"(b8), "r"(c));
    return d;
}
__device__ __forceinline__ int dp2a_hi(unsigned a16, unsigned b8, int c) {
    int d;
    asm("dp2a.hi.s32.s32 %0, %1, %2, %3;" : "=r"(d) : "r"(a16), "r"(b8), "r"(c));
    return d;
}

// ---------------- Phase 1: build quantized table, one warp per row ----------------
__global__ __launch_bounds__(BLD_THREADS, 4)
void build_comb_kernel(const float* __restrict__ W_ft,
                       const float* __restrict__ W_fft)
{
    const int wid  = threadIdx.x >> 5;
    const int lane = threadIdx.x & 31;
    const int f    = blockIdx.x * 8 + wid;          // NFEAT/8 blocks

    const float4* wrow = (const float4*)(W_ft  + (size_t)f * FT_OUT);
    const float4* vrow = (const float4*)(W_fft + (size_t)(f % NVFEAT) * FT_OUT);

    // 1024 floats / warp: each lane 8 float4 chunks (coalesced per chunk)
    float4 w[8];
    #pragma unroll
    for (int k = 0; k < 8; k++) {
        float4 a = __ldcs(wrow + k * 32 + lane);    // stream W_ft, evict-first
        float4 v = __ldg (vrow + k * 32 + lane);
        w[k] = make_float4(a.x + v.x, a.y + v.y, a.z + v.z, a.w + v.w);
    }

    float m = 0.f;
    #pragma unroll
    for (int k = 0; k < 8; k++)
        m = fmaxf(m, fmaxf(fmaxf(fabsf(w[k].x), fabsf(w[k].y)),
                           fmaxf(fabsf(w[k].z), fabsf(w[k].w))));
    #pragma unroll
    for (int off = 16; off > 0; off >>= 1)
        m = fmaxf(m, __shfl_xor_sync(0xffffffffu, m, off));
    m = fmaxf(m, 1e-30f);
    if (lane == 0) g_scale[f] = m * (1.0f / 127.0f);
    const float inv = 127.0f / m;

    char4* qrow = (char4*)(g_qtab + (size_t)f * FT_OUT);
    #pragma unroll
    for (int k = 0; k < 8; k++) {
        char4 q;
        q.x = (signed char)__float2int_rn(w[k].x * inv);
        q.y = (signed char)__float2int_rn(w[k].y * inv);
        q.z = (signed char)__float2int_rn(w[k].z * inv);
        q.w = (signed char)__float2int_rn(w[k].w * inv);
        qrow[k * 32 + lane] = q;
    }
}

// ---------------- Phase 2: gather + dp2a accumulate + epilogue ----------------
__global__ __launch_bounds__(GTH_THREADS, 10)
void nnue_gather_kernel(
    const float* __restrict__ values,     // [NNZ]
    const int*   __restrict__ stm_feat,   // [NNZ]
    const int*   __restrict__ nstm_feat,  // [NNZ]
    const float* __restrict__ b_ft,       // [1024]
    const float* __restrict__ b_fft,      // [1024]
    const float* __restrict__ W_out,      // [2048]
    const float* __restrict__ b_out,      // [1]
    float*       __restrict__ out)        // [B]
{
    __shared__ __align__(16) int s_off[2 * FPP];  // byte offsets; [0,32)=stm, [32,64)=nstm
    __shared__ float    s_a[2 * FPP];             // a_f = v * row_scale
    __shared__ unsigned s_u16[2 * (FPP / 2)];     // packed s16x2; [0,16)=stm, [16,32)=nstm
    __shared__ float    s_Tf;
    __shared__ float    s_red[GTH_THREADS / 32];

    const int b   = blockIdx.x;
    const int tid = threadIdx.x;

    if (tid < FPP) {
        const int fs = stm_feat[b * FPP + tid];
        const int fn = nstm_feat[b * FPP + tid];
        const float v = values[b * FPP + tid];
        s_off[tid]       = fs << 10;              // *1024 B/row
        s_off[FPP + tid] = fn << 10;
        s_a[tid]         = v * __ldg(g_scale + fs);
        s_a[FPP + tid]   = v * __ldg(g_scale + fn);
    }
    __syncthreads();

    // warp 0: block max |a|, then pack s16 multipliers (one chunk of 2 feats per lane)
    if (tid < 32) {
        float m = fmaxf(fabsf(s_a[tid]), fabsf(s_a[tid + 32]));
        #pragma unroll
        for (int off = 16; off > 0; off >>= 1)
            m = fmaxf(m, __shfl_xor_sync(0xffffffffu, m, off));
        const float T = fmaxf(m, 1e-30f);
        const float invT = 32767.0f / T;
        if (tid == 0) s_Tf = T * (1.0f / 32767.0f);

        const int side = tid >> 4;                 // 0: stm chunks, 1: nstm chunks
        const int c    = tid & 15;
        const int base = side * FPP + 2 * c;
        const int u0 = __float2int_rn(s_a[base]     * invT);
        const int u1 = __float2int_rn(s_a[base + 1] * invT);
        s_u16[tid] = (unsigned)(u0 & 0xFFFF) | ((unsigned)u1 << 16);
    }
    __syncthreads();

    const char* base = (const char*)g_qtab + tid * 8;   // this thread's 8 dims

    int accs[8] = {0,0,0,0,0,0,0,0};
    int accn[8] = {0,0,0,0,0,0,0,0};

    // 16 chunks; each: 2 stm feats + 2 nstm feats (4 independent 8B loads)
    #pragma unroll 4
    for (int c = 0; c < FPP / 2; c++) {
        const int2 offs = *(const int2*)&s_off[2 * c];
        const int2 offn = *(const int2*)&s_off[FPP + 2 * c];
        const unsigned us = s_u16[c];
        const unsigned un = s_u16[16 + c];

        const uint2 q0 = __ldcg((const uint2*)(base + offs.x));
        const uint2 q1 = __ldcg((const uint2*)(base + offs.y));
        const uint2 r0 = __ldcg((const uint2*)(base + offn.x));
        const uint2 r1 = __ldcg((const uint2*)(base + offn.y));

        // stm, dims 0-3: t = {f0d0,f1d0,f0d1,f1d1}, tb = {f0d2,f1d2,f0d3,f1d3}
        unsigned t, tb;
        t  = __byte_perm(q0.x, q1.x, 0x5140);
        tb = __byte_perm(q0.x, q1.x, 0x7362);
        accs[0] = dp2a_lo(us, t,  accs[0]);
        accs[1] = dp2a_hi(us, t,  accs[1]);
        accs[2] = dp2a_lo(us, tb, accs[2]);
        accs[3] = dp2a_hi(us, tb, accs[3]);
        // stm, dims 4-7
        t  = __byte_perm(q0.y, q1.y, 0x5140);
        tb = __byte_perm(q0.y, q1.y, 0x7362);
        accs[4] = dp2a_lo(us, t,  accs[4]);
        accs[5] = dp2a_hi(us, t,  accs[5]);
        accs[6] = dp2a_lo(us, tb, accs[6]);
        accs[7] = dp2a_hi(us, tb, accs[7]);
        // nstm, dims 0-3
        t  = __byte_perm(r0.x, r1.x, 0x5140);
        tb = __byte_perm(r0.x, r1.x, 0x7362);
        accn[0] = dp2a_lo(un, t,  accn[0]);
        accn[1] = dp2a_hi(un, t,  accn[1]);
        accn[2] = dp2a_lo(un, tb, accn[2]);
        accn[3] = dp2a_hi(un, tb, accn[3]);
        // nstm, dims 4-7
        t  = __byte_perm(r0.y, r1.y, 0x5140);
        tb = __byte_perm(r0.y, r1.y, 0x7362);
        accn[4] = dp2a_lo(un, t,  accn[4]);
        accn[5] = dp2a_hi(un, t,  accn[5]);
        accn[6] = dp2a_lo(un, tb, accn[6]);
        accn[7] = dp2a_hi(un, tb, accn[7]);
    }

    // epilogue: hidden = bias + Tf*acc; clip; partial output dot
    const float Tf = s_Tf;
    const int d = tid * 8;
    float p = 0.f;
    {
        float4 bf0 = *(const float4*)(b_ft  + d);
        float4 bf1 = *(const float4*)(b_ft  + d + 4);
        float4 bb0 = *(const float4*)(b_fft + d);
        float4 bb1 = *(const float4*)(b_fft + d + 4);
        float bias[8] = {bf0.x + bb0.x, bf0.y + bb0.y, bf0.z + bb0.z, bf0.w + bb0.w,
                         bf1.x + bb1.x, bf1.y + bb1.y, bf1.z + bb1.z, bf1.w + bb1.w};

        float4 ws0 = *(const float4*)(W_out + d);
        float4 ws1 = *(const float4*)(W_out + d + 4);
        float4 wn0 = *(const float4*)(W_out + FT_OUT + d);
        float4 wn1 = *(const float4*)(W_out + FT_OUT + d + 4);
        float ws[8] = {ws0.x, ws0.y, ws0.z, ws0.w, ws1.x, ws1.y, ws1.z, ws1.w};
        float wn[8] = {wn0.x, wn0.y, wn0.z, wn0.w, wn1.x, wn1.y, wn1.z, wn1.w};

        #pragma unroll
        for (int j = 0; j < 8; j++) {
            float hs = fmaf((float)accs[j], Tf, bias[j]);
            float hn = fmaf((float)accn[j], Tf, bias[j]);
            p = fmaf(fminf(fmaxf(hs, 0.f), 1.f), ws[j], p);
            p = fmaf(fminf(fmaxf(hn, 0.f), 1.f), wn[j], p);
        }
    }

    // warp reduce (4 warps)
    #pragma unroll
    for (int off = 16; off > 0; off >>= 1)
        p += __shfl_down_sync(0xffffffffu, p, off);
    if ((tid & 31) == 0) s_red[tid >> 5] = p;
    __syncthreads();

    if (tid < (GTH_THREADS / 32)) {
        float q = s_red[tid];
        #pragma unroll
        for (int off = (GTH_THREADS / 64); off > 0; off >>= 1)
            q += __shfl_down_sync(0xfu, q, off);
        if (tid == 0) {
            float x = q + b_out[0];
            out[b] = 1.0f / (1.0f + expf(-x));
        }
    }
}

extern "C" void kernel_launch(void* const* d_in, const int* in_sizes, int n_in,
                              void* d_out, int out_size) {
    // metadata order:
    // 0 values, 1 stm_feat, 2 nstm_feat, 3 batch_idx, 4 W_ft, 5 b_ft,
    // 6 W_fft, 7 b_fft, 8 W_out, 9 b_out, 10 size
    const float* values    = (const float*)d_in[0];
    const int*   stm_feat  = (const int*)d_in[1];
    const int*   nstm_feat = (const int*)d_in[2];
    const float* W_ft      = (const float*)d_in[4];
    const float* b_ft      = (const float*)d_in[5];
    const float* W_fft     = (const float*)d_in[6];
    const float* b_fft     = (const float*)d_in[7];
    const float* W_out     = (const float*)d_in[8];
    const float* b_out     = (const float*)d_in[9];
    float* out = (float*)d_out;

    const int B = out_size;  // 8192

    build_comb_kernel<<<NFEAT / 8, BLD_THREADS>>>(W_ft, W_fft);
    nnue_gather_kernel<<<B, GTH_THREADS>>>(values, stm_feat, nstm_feat,
                                           b_ft, b_fft, W_out, b_out, out);
}

// round 13
// speedup vs baseline: 1.5739x; 1.0051x over previous
#include <cuda_runtime.h>
#include <cuda_bf16.h>
#include <math.h>

// NNUE HalfKA inference, two-phase, int8 table + s16 multipliers + DP2A:
//  Phase 1 (warp-per-row): comb = W_ft[f] + W_fft[f % 768];
//           s[f] = maxabs/127; q[f] = rint(comb/s) int8  (48 MB, L2-resident)
//  Phase 2: per batch element: a_f = v_f * s[feat_f]; T = max|a|;
//           u16_f = rint(a_f * 32767 / T)  (s16, ~exact)
//           acc_d  = sum_f q[f,d] * u16_f   -- integer, PRMT transpose + dp2a
//           hidden = bias + (T/32767) * acc; clip; output dot; sigmoid.
//  R12 tune: occupancy 62->75% (launch_bounds 128,12) + full unroll with
//  2-chunk load batching (8 LDGs in flight) to hide L2-hit latency.

#define FT_OUT   1024
#define FPP      32
#define NVFEAT   768
#define NFEAT    49152
#define BLD_THREADS 256           // 8 warps = 8 rows per block
#define GTH_THREADS 128           // 128 threads * 8 dims (8 B int8) = one row

// 48 MB quantized combined table + per-row scales (static device scratch)
__device__ __align__(16) signed char g_qtab[(size_t)NFEAT * FT_OUT];
__device__ float g_scale[NFEAT];

__device__ __forceinline__ int dp2a_lo(unsigned a16, unsigned b8, int c) {
    int d;
    asm("dp2a.lo.s32.s32 %0, %1, %2, %3;" : "=r"(d) : "r"(a16), "r"(b8), "r"(c));
    return d;
}
__device__ __forceinline__ int dp2a_hi(unsigned a16, unsigned b8, int c) {
    int d;
    asm("dp2a.hi.s32.s32 %0, %1, %2, %3;" : "=r"(d) : "r"(a16), "r"(b8), "r"(c));
    return d;
}

// ---------------- Phase 1: build quantized table, one warp per row ----------------
__global__ __launch_bounds__(BLD_THREADS, 4)
void build_comb_kernel(const float* __restrict__ W_ft,
                       const float* __restrict__ W_fft)
{
    const int wid  = threadIdx.x >> 5;
    const int lane = threadIdx.x & 31;
    const int f    = blockIdx.x * 8 + wid;          // NFEAT/8 blocks

    const float4* wrow = (const float4*)(W_ft  + (size_t)f * FT_OUT);
    const float4* vrow = (const float4*)(W_fft + (size_t)(f % NVFEAT) * FT_OUT);

    // 1024 floats / warp: each lane 8 float4 chunks (coalesced per chunk)
    float4 w[8];
    #pragma unroll
    for (int k = 0; k < 8; k++) {
        float4 a = __ldcs(wrow + k * 32 + lane);    // stream W_ft, evict-first
        float4 v = __ldg (vrow + k * 32 + lane);
        w[k] = make_float4(a.x + v.x, a.y + v.y, a.z + v.z, a.w + v.w);
    }

    float m = 0.f;
    #pragma unroll
    for (int k = 0; k < 8; k++)
        m = fmaxf(m, fmaxf(fmaxf(fabsf(w[k].x), fabsf(w[k].y)),
                           fmaxf(fabsf(w[k].z), fabsf(w[k].w))));
    #pragma unroll
    for (int off = 16; off > 0; off >>= 1)
        m = fmaxf(m, __shfl_xor_sync(0xffffffffu, m, off));
    m = fmaxf(m, 1e-30f);
    if (lane == 0) g_scale[f] = m * (1.0f / 127.0f);
    const float inv = 127.0f / m;

    char4* qrow = (char4*)(g_qtab + (size_t)f * FT_OUT);
    #pragma unroll
    for (int k = 0; k < 8; k++) {
        char4 q;
        q.x = (signed char)__float2int_rn(w[k].x * inv);
        q.y = (signed char)__float2int_rn(w[k].y * inv);
        q.z = (signed char)__float2int_rn(w[k].z * inv);
        q.w = (signed char)__float2int_rn(w[k].w * inv);
        qrow[k * 32 + lane] = q;
    }
}

// process one side's 2-feature chunk: PRMT transpose + 8 dp2a into acc[8]
__device__ __forceinline__ void dp2a_chunk(const uint2& q0, const uint2& q1,
                                           unsigned u, int* acc) {
    unsigned t, tb;
    t  = __byte_perm(q0.x, q1.x, 0x5140);
    tb = __byte_perm(q0.x, q1.x, 0x7362);
    acc[0] = dp2a_lo(u, t,  acc[0]);
    acc[1] = dp2a_hi(u, t,  acc[1]);
    acc[2] = dp2a_lo(u, tb, acc[2]);
    acc[3] = dp2a_hi(u, tb, acc[3]);
    t  = __byte_perm(q0.y, q1.y, 0x5140);
    tb = __byte_perm(q0.y, q1.y, 0x7362);
    acc[4] = dp2a_lo(u, t,  acc[4]);
    acc[5] = dp2a_hi(u, t,  acc[5]);
    acc[6] = dp2a_lo(u, tb, acc[6]);
    acc[7] = dp2a_hi(u, tb, acc[7]);
}

// ---------------- Phase 2: gather + dp2a accumulate + epilogue ----------------
__global__ __launch_bounds__(GTH_THREADS, 12)
void nnue_gather_kernel(
    const float* __restrict__ values,     // [NNZ]
    const int*   __restrict__ stm_feat,   // [NNZ]
    const int*   __restrict__ nstm_feat,  // [NNZ]
    const float* __restrict__ b_ft,       // [1024]
    const float* __restrict__ b_fft,      // [1024]
    const float* __restrict__ W_out,      // [2048]
    const float* __restrict__ b_out,      // [1]
    float*       __restrict__ out)        // [B]
{
    __shared__ __align__(16) int s_off[2 * FPP];  // byte offsets; [0,32)=stm, [32,64)=nstm
    __shared__ float    s_a[2 * FPP];             // a_f = v * row_scale
    __shared__ unsigned s_u16[2 * (FPP / 2)];     // packed s16x2; [0,16)=stm, [16,32)=nstm
    __shared__ float    s_Tf;
    __shared__ float    s_red[GTH_THREADS / 32];

    const int b   = blockIdx.x;
    const int tid = threadIdx.x;

    if (tid < FPP) {
        const int fs = stm_feat[b * FPP + tid];
        const int fn = nstm_feat[b * FPP + tid];
        const float v = values[b * FPP + tid];
        s_off[tid]       = fs << 10;              // *1024 B/row
        s_off[FPP + tid] = fn << 10;
        s_a[tid]         = v * __ldg(g_scale + fs);
        s_a[FPP + tid]   = v * __ldg(g_scale + fn);
    }
    __syncthreads();

    // warp 0: block max |a|, then pack s16 multipliers (one chunk of 2 feats per lane)
    if (tid < 32) {
        float m = fmaxf(fabsf(s_a[tid]), fabsf(s_a[tid + 32]));
        #pragma unroll
        for (int off = 16; off > 0; off >>= 1)
            m = fmaxf(m, __shfl_xor_sync(0xffffffffu, m, off));
        const float T = fmaxf(m, 1e-30f);
        const float invT = 32767.0f / T;
        if (tid == 0) s_Tf = T * (1.0f / 32767.0f);

        const int side = tid >> 4;                 // 0: stm chunks, 1: nstm chunks
        const int c    = tid & 15;
        const int base = side * FPP + 2 * c;
        const int u0 = __float2int_rn(s_a[base]     * invT);
        const int u1 = __float2int_rn(s_a[base + 1] * invT);
        s_u16[tid] = (unsigned)(u0 & 0xFFFF) | ((unsigned)u1 << 16);
    }
    __syncthreads();

    const char* base = (const char*)g_qtab + tid * 8;   // this thread's 8 dims

    int accs[8] = {0,0,0,0,0,0,0,0};
    int accn[8] = {0,0,0,0,0,0,0,0};

    // 8 superchunks; each batches 8 independent 8B loads (2 chunks x 4 loads)
    // before any consumer -> high front-batched MLP per warp.
    #pragma unroll
    for (int cc = 0; cc < FPP / 4; cc++) {
        const int c0 = 2 * cc;
        const int c1 = 2 * cc + 1;
        const int4 offs = *(const int4*)&s_off[2 * c0];        // 2 stm chunks
        const int4 offn = *(const int4*)&s_off[FPP + 2 * c0];  // 2 nstm chunks

        const uint2 qa0 = __ldcg((const uint2*)(base + offs.x));
        const uint2 qa1 = __ldcg((const uint2*)(base + offs.y));
        const uint2 qb0 = __ldcg((const uint2*)(base + offs.z));
        const uint2 qb1 = __ldcg((const uint2*)(base + offs.w));
        const uint2 ra0 = __ldcg((const uint2*)(base + offn.x));
        const uint2 ra1 = __ldcg((const uint2*)(base + offn.y));
        const uint2 rb0 = __ldcg((const uint2*)(base + offn.z));
        const uint2 rb1 = __ldcg((const uint2*)(base + offn.w));

        dp2a_chunk(qa0, qa1, s_u16[c0],      accs);
        dp2a_chunk(qb0, qb1, s_u16[c1],      accs);
        dp2a_chunk(ra0, ra1, s_u16[16 + c0], accn);
        dp2a_chunk(rb0, rb1, s_u16[16 + c1], accn);
    }

    // epilogue: hidden = bias + Tf*acc; clip; partial output dot
    const float Tf = s_Tf;
    const int d = tid * 8;
    float p = 0.f;
    {
        float4 bf0 = *(const float4*)(b_ft  + d);
        float4 bf1 = *(const float4*)(b_ft  + d + 4);
        float4 bb0 = *(const float4*)(b_fft + d);
        float4 bb1 = *(const float4*)(b_fft + d + 4);
        float bias[8] = {bf0.x + bb0.x, bf0.y + bb0.y, bf0.z + bb0.z, bf0.w + bb0.w,
                         bf1.x + bb1.x, bf1.y + bb1.y, bf1.z + bb1.z, bf1.w + bb1.w};

        float4 ws0 = *(const float4*)(W_out + d);
        float4 ws1 = *(const float4*)(W_out + d + 4);
        float4 wn0 = *(const float4*)(W_out + FT_OUT + d);
        float4 wn1 = *(const float4*)(W_out + FT_OUT + d + 4);
        float ws[8] = {ws0.x, ws0.y, ws0.z, ws0.w, ws1.x, ws1.y, ws1.z, ws1.w};
        float wn[8] = {wn0.x, wn0.y, wn0.z, wn0.w, wn1.x, wn1.y, wn1.z, wn1.w};

        #pragma unroll
        for (int j = 0; j < 8; j++) {
            float hs = fmaf((float)accs[j], Tf, bias[j]);
            float hn = fmaf((float)accn[j], Tf, bias[j]);
            p = fmaf(fminf(fmaxf(hs, 0.f), 1.f), ws[j], p);
            p = fmaf(fminf(fmaxf(hn, 0.f), 1.f), wn[j], p);
        }
    }

    // warp reduce (4 warps)
    #pragma unroll
    for (int off = 16; off > 0; off >>= 1)
        p += __shfl_down_sync(0xffffffffu, p, off);
    if ((tid & 31) == 0) s_red[tid >> 5] = p;
    __syncthreads();

    if (tid < (GTH_THREADS / 32)) {
        float q = s_red[tid];
        #pragma unroll
        for (int off = (GTH_THREADS / 64); off > 0; off >>= 1)
            q += __shfl_down_sync(0xfu, q, off);
        if (tid == 0) {
            float x = q + b_out[0];
            out[b] = 1.0f / (1.0f + expf(-x));
        }
    }
}

extern "C" void kernel_launch(void* const* d_in, const int* in_sizes, int n_in,
                              void* d_out, int out_size) {
    // metadata order:
    // 0 values, 1 stm_feat, 2 nstm_feat, 3 batch_idx, 4 W_ft, 5 b_ft,
    // 6 W_fft, 7 b_fft, 8 W_out, 9 b_out, 10 size
    const float* values    = (const float*)d_in[0];
    const int*   stm_feat  = (const int*)d_in[1];
    const int*   nstm_feat = (const int*)d_in[2];
    const float* W_ft      = (const float*)d_in[4];
    const float* b_ft      = (const float*)d_in[5];
    const float* W_fft     = (const float*)d_in[6];
    const float* b_fft     = (const float*)d_in[7];
    const float* W_out     = (const float*)d_in[8];
    const float* b_out     = (const float*)d_in[9];
    float* out = (float*)d_out;

    const int B = out_size;  // 8192

    build_comb_kernel<<<NFEAT / 8, BLD_THREADS>>>(W_ft, W_fft);
    nnue_gather_kernel<<<B, GTH_THREADS>>>(values, stm_feat, nstm_feat,
                                           b_ft, b_fft, W_out, b_out, out);
}

// round 15
// speedup vs baseline: 1.6193x; 1.0288x over previous
#include <cuda_runtime.h>
#include <cuda_bf16.h>
#include <math.h>

// NNUE HalfKA inference, two-phase, int8 table + s16 multipliers + DP2A + PDL:
//  Phase 1 (warp-per-row): comb = W_ft[f] + W_fft[f % 768];
//           s[f] = maxabs/127; q[f] = rint(comb/s) int8  (48 MB, L2-resident)
//  Phase 2: per batch element: a_f = v_f * s[feat_f]; T = max|a|;
//           u16_f = rint(a_f * 32767 / T); acc_d = sum_f q[f,d]*u16_f (dp2a);
//           hidden = bias + (T/32767)*acc; clip; output dot; sigmoid.
//  Both phases sit at their rooflines (build: DRAM ~7.5 TB/s; gather: LTS ~11.4
//  TB/s). PDL lets gather CTAs launch during the build tail and overlap their
//  build-independent prologue; griddepcontrol.wait gates table/scale reads.

#define FT_OUT   1024
#define FPP      32
#define NVFEAT   768
#define NFEAT    49152
#define BLD_THREADS 256           // 8 warps = 8 rows per block
#define GTH_THREADS 128           // 128 threads * 8 dims (8 B int8) = one row

// 48 MB quantized combined table + per-row scales (static device scratch)
__device__ __align__(16) signed char g_qtab[(size_t)NFEAT * FT_OUT];
__device__ float g_scale[NFEAT];

__device__ __forceinline__ int dp2a_lo(unsigned a16, unsigned b8, int c) {
    int d;
    asm("dp2a.lo.s32.s32 %0, %1, %2, %3;" : "=r"(d) : "r"(a16), "r"(b8), "r"(c));
    return d;
}
__device__ __forceinline__ int dp2a_hi(unsigned a16, unsigned b8, int c) {
    int d;
    asm("dp2a.hi.s32.s32 %0, %1, %2, %3;" : "=r"(d) : "r"(a16), "r"(b8), "r"(c));
    return d;
}

// ---------------- Phase 1: build quantized table, one warp per row ----------------
__global__ __launch_bounds__(BLD_THREADS, 4)
void build_comb_kernel(const float* __restrict__ W_ft,
                       const float* __restrict__ W_fft)
{
    const int wid  = threadIdx.x >> 5;
    const int lane = threadIdx.x & 31;
    const int f    = blockIdx.x * 8 + wid;          // NFEAT/8 blocks

    const float4* wrow = (const float4*)(W_ft  + (size_t)f * FT_OUT);
    const float4* vrow = (const float4*)(W_fft + (size_t)(f % NVFEAT) * FT_OUT);

    // 1024 floats / warp: each lane 8 float4 chunks (coalesced per chunk)
    float4 w[8];
    #pragma unroll
    for (int k = 0; k < 8; k++) {
        float4 a = __ldcs(wrow + k * 32 + lane);    // stream W_ft, evict-first
        float4 v = __ldg (vrow + k * 32 + lane);
        w[k] = make_float4(a.x + v.x, a.y + v.y, a.z + v.z, a.w + v.w);
    }

    float m = 0.f;
    #pragma unroll
    for (int k = 0; k < 8; k++)
        m = fmaxf(m, fmaxf(fmaxf(fabsf(w[k].x), fabsf(w[k].y)),
                           fmaxf(fabsf(w[k].z), fabsf(w[k].w))));
    #pragma unroll
    for (int off = 16; off > 0; off >>= 1)
        m = fmaxf(m, __shfl_xor_sync(0xffffffffu, m, off));
    m = fmaxf(m, 1e-30f);
    if (lane == 0) g_scale[f] = m * (1.0f / 127.0f);
    const float inv = 127.0f / m;

    // PDL: allow dependent (gather) grid to start launching; its pre-wait
    // prologue overlaps our remaining stores. The dependent's
    // griddepcontrol.wait (full-grid completion) provides memory safety.
    asm volatile("griddepcontrol.launch_dependents;");

    char4* qrow = (char4*)(g_qtab + (size_t)f * FT_OUT);
    #pragma unroll
    for (int k = 0; k < 8; k++) {
        char4 q;
        q.x = (signed char)__float2int_rn(w[k].x * inv);
        q.y = (signed char)__float2int_rn(w[k].y * inv);
        q.z = (signed char)__float2int_rn(w[k].z * inv);
        q.w = (signed char)__float2int_rn(w[k].w * inv);
        qrow[k * 32 + lane] = q;
    }
}

// process one side's 2-feature chunk: PRMT transpose + 8 dp2a into acc[8]
__device__ __forceinline__ void dp2a_chunk(const uint2& q0, const uint2& q1,
                                           unsigned u, int* acc) {
    unsigned t, tb;
    t  = __byte_perm(q0.x, q1.x, 0x5140);
    tb = __byte_perm(q0.x, q1.x, 0x7362);
    acc[0] = dp2a_lo(u, t,  acc[0]);
    acc[1] = dp2a_hi(u, t,  acc[1]);
    acc[2] = dp2a_lo(u, tb, acc[2]);
    acc[3] = dp2a_hi(u, tb, acc[3]);
    t  = __byte_perm(q0.y, q1.y, 0x5140);
    tb = __byte_perm(q0.y, q1.y, 0x7362);
    acc[4] = dp2a_lo(u, t,  acc[4]);
    acc[5] = dp2a_hi(u, t,  acc[5]);
    acc[6] = dp2a_lo(u, tb, acc[6]);
    acc[7] = dp2a_hi(u, tb, acc[7]);
}

// ---------------- Phase 2: gather + dp2a accumulate + epilogue ----------------
__global__ __launch_bounds__(GTH_THREADS, 12)
void nnue_gather_kernel(
    const float* __restrict__ values,     // [NNZ]
    const int*   __restrict__ stm_feat,   // [NNZ]
    const int*   __restrict__ nstm_feat,  // [NNZ]
    const float* __restrict__ b_ft,       // [1024]
    const float* __restrict__ b_fft,      // [1024]
    const float* __restrict__ W_out,      // [2048]
    const float* __restrict__ b_out,      // [1]
    float*       __restrict__ out)        // [B]
{
    __shared__ __align__(16) int s_off[2 * FPP];  // byte offsets; [0,32)=stm, [32,64)=nstm
    __shared__ float    s_v[FPP];                 // raw values
    __shared__ float    s_a[2 * FPP];             // a_f = v * row_scale
    __shared__ unsigned s_u16[2 * (FPP / 2)];     // packed s16x2; [0,16)=stm, [16,32)=nstm
    __shared__ float    s_Tf;
    __shared__ float    s_red[GTH_THREADS / 32];

    const int b   = blockIdx.x;
    const int tid = threadIdx.x;

    int fs = 0, fn = 0;
    // ---- build-independent prologue (overlaps build tail under PDL) ----
    if (tid < FPP) {
        fs = stm_feat[b * FPP + tid];
        fn = nstm_feat[b * FPP + tid];
        s_v[tid]         = values[b * FPP + tid];
        s_off[tid]       = fs << 10;              // *1024 B/row
        s_off[FPP + tid] = fn << 10;
    }

    // ---- wait for build grid completion before touching table / scales ----
    asm volatile("griddepcontrol.wait;" ::: "memory");

    if (tid < FPP) {
        const float v = s_v[tid];
        s_a[tid]       = v * __ldg(g_scale + fs);
        s_a[FPP + tid] = v * __ldg(g_scale + fn);
    }
    __syncthreads();

    // warp 0: block max |a|, then pack s16 multipliers (one chunk of 2 feats per lane)
    if (tid < 32) {
        float m = fmaxf(fabsf(s_a[tid]), fabsf(s_a[tid + 32]));
        #pragma unroll
        for (int off = 16; off > 0; off >>= 1)
            m = fmaxf(m, __shfl_xor_sync(0xffffffffu, m, off));
        const float T = fmaxf(m, 1e-30f);
        const float invT = 32767.0f / T;
        if (tid == 0) s_Tf = T * (1.0f / 32767.0f);

        const int side = tid >> 4;                 // 0: stm chunks, 1: nstm chunks
        const int c    = tid & 15;
        const int base = side * FPP + 2 * c;
        const int u0 = __float2int_rn(s_a[base]     * invT);
        const int u1 = __float2int_rn(s_a[base + 1] * invT);
        s_u16[tid] = (unsigned)(u0 & 0xFFFF) | ((unsigned)u1 << 16);
    }
    __syncthreads();

    const char* base = (const char*)g_qtab + tid * 8;   // this thread's 8 dims

    int accs[8] = {0,0,0,0,0,0,0,0};
    int accn[8] = {0,0,0,0,0,0,0,0};

    // 8 superchunks; each batches 8 independent 8B loads (2 chunks x 4 loads)
    #pragma unroll
    for (int cc = 0; cc < FPP / 4; cc++) {
        const int c0 = 2 * cc;
        const int c1 = 2 * cc + 1;
        const int4 offs = *(const int4*)&s_off[2 * c0];        // 2 stm chunks
        const int4 offn = *(const int4*)&s_off[FPP + 2 * c0];  // 2 nstm chunks

        const uint2 qa0 = __ldcg((const uint2*)(base + offs.x));
        const uint2 qa1 = __ldcg((const uint2*)(base + offs.y));
        const uint2 qb0 = __ldcg((const uint2*)(base + offs.z));
        const uint2 qb1 = __ldcg((const uint2*)(base + offs.w));
        const uint2 ra0 = __ldcg((const uint2*)(base + offn.x));
        const uint2 ra1 = __ldcg((const uint2*)(base + offn.y));
        const uint2 rb0 = __ldcg((const uint2*)(base + offn.z));
        const uint2 rb1 = __ldcg((const uint2*)(base + offn.w));

        dp2a_chunk(qa0, qa1, s_u16[c0],      accs);
        dp2a_chunk(qb0, qb1, s_u16[c1],      accs);
        dp2a_chunk(ra0, ra1, s_u16[16 + c0], accn);
        dp2a_chunk(rb0, rb1, s_u16[16 + c1], accn);
    }

    // epilogue: hidden = bias + Tf*acc; clip; partial output dot
    const float Tf = s_Tf;
    const int d = tid * 8;
    float p = 0.f;
    {
        float4 bf0 = *(const float4*)(b_ft  + d);
        float4 bf1 = *(const float4*)(b_ft  + d + 4);
        float4 bb0 = *(const float4*)(b_fft + d);
        float4 bb1 = *(const float4*)(b_fft + d + 4);
        float bias[8] = {bf0.x + bb0.x, bf0.y + bb0.y, bf0.z + bb0.z, bf0.w + bb0.w,
                         bf1.x + bb1.x, bf1.y + bb1.y, bf1.z + bb1.z, bf1.w + bb1.w};

        float4 ws0 = *(const float4*)(W_out + d);
        float4 ws1 = *(const float4*)(W_out + d + 4);
        float4 wn0 = *(const float4*)(W_out + FT_OUT + d);
        float4 wn1 = *(const float4*)(W_out + FT_OUT + d + 4);
        float ws[8] = {ws0.x, ws0.y, ws0.z, ws0.w, ws1.x, ws1.y, ws1.z, ws1.w};
        float wn[8] = {wn0.x, wn0.y, wn0.z, wn0.w, wn1.x, wn1.y, wn1.z, wn1.w};

        #pragma unroll
        for (int j = 0; j < 8; j++) {
            float hs = fmaf((float)accs[j], Tf, bias[j]);
            float hn = fmaf((float)accn[j], Tf, bias[j]);
            p = fmaf(fminf(fmaxf(hs, 0.f), 1.f), ws[j], p);
            p = fmaf(fminf(fmaxf(hn, 0.f), 1.f), wn[j], p);
        }
    }

    // warp reduce (4 warps)
    #pragma unroll
    for (int off = 16; off > 0; off >>= 1)
        p += __shfl_down_sync(0xffffffffu, p, off);
    if ((tid & 31) == 0) s_red[tid >> 5] = p;
    __syncthreads();

    if (tid < (GTH_THREADS / 32)) {
        float q = s_red[tid];
        #pragma unroll
        for (int off = (GTH_THREADS / 64); off > 0; off >>= 1)
            q += __shfl_down_sync(0xfu, q, off);
        if (tid == 0) {
            float x = q + b_out[0];
            out[b] = 1.0f / (1.0f + expf(-x));
        }
    }
}

extern "C" void kernel_launch(void* const* d_in, const int* in_sizes, int n_in,
                              void* d_out, int out_size) {
    // metadata order:
    // 0 values, 1 stm_feat, 2 nstm_feat, 3 batch_idx, 4 W_ft, 5 b_ft,
    // 6 W_fft, 7 b_fft, 8 W_out, 9 b_out, 10 size
    const float* values    = (const float*)d_in[0];
    const int*   stm_feat  = (const int*)d_in[1];
    const int*   nstm_feat = (const int*)d_in[2];
    const float* W_ft      = (const float*)d_in[4];
    const float* b_ft      = (const float*)d_in[5];
    const float* W_fft     = (const float*)d_in[6];
    const float* b_fft     = (const float*)d_in[7];
    const float* W_out     = (const float*)d_in[8];
    const float* b_out     = (const float*)d_in[9];
    float* out = (float*)d_out;

    const int B = out_size;  // 8192

    build_comb_kernel<<<NFEAT / 8, BLD_THREADS>>>(W_ft, W_fft);

    // Gather launched with Programmatic Stream Serialization: it may begin
    // launching while build's tail CTAs run; griddepcontrol.wait inside the
    // kernel enforces the data dependency.
    {
        cudaLaunchConfig_t cfg = {};
        cfg.gridDim  = dim3(B, 1, 1);
        cfg.blockDim = dim3(GTH_THREADS, 1, 1);
        cfg.dynamicSmemBytes = 0;
        cfg.stream = 0;
        cudaLaunchAttribute attr[1];
        attr[0].id = cudaLaunchAttributeProgrammaticStreamSerialization;
        attr[0].val.programmaticStreamSerializationAllowed = 1;
        cfg.attrs = attr;
        cfg.numAttrs = 1;
        cudaLaunchKernelEx(&cfg, nnue_gather_kernel,
                           values, stm_feat, nstm_feat,
                           b_ft, b_fft, W_out, b_out, out);
    }
}